// round 10
// baseline (speedup 1.0000x reference)
#include <cuda_runtime.h>
#include <math.h>

#define B_SZ 2048
#define T_SZ 200
#define NB   16

typedef unsigned long long u64;

// ---- packed fp32x2 helpers (SASS FFMA2: only reachable via PTX) ----
__device__ __forceinline__ void ffma2(u64 &d, u64 a, u64 b){
    asm("fma.rn.f32x2 %0, %1, %2, %0;" : "+l"(d) : "l"(a), "l"(b));
}
__device__ __forceinline__ u64 pack2(float lo, float hi){
    u64 r; asm("mov.b64 %0, {%1, %2};" : "=l"(r) : "f"(lo), "f"(hi)); return r;
}
__device__ __forceinline__ float2 unpack2(u64 v){
    float2 r; asm("mov.b64 {%0, %1}, %2;" : "=f"(r.x), "=f"(r.y) : "l"(v)); return r;
}

// ---------------- device scratch (no runtime allocation allowed) ----------------
__device__ __align__(16) float g_l1_whhT[2][128*512];
__device__ __align__(16) float g_l1_wih [2][512];
__device__ __align__(16) float g_l1_b   [2][512];
__device__ __align__(16) float g_l2_wihT[2][256*512];
__device__ __align__(16) float g_l2_whhT[2][128*512];
__device__ __align__(16) float g_l2_b   [2][512];
__device__ __align__(16) float g_fc1_wT[256*256];
__device__ __align__(16) float g_fc2_wT[256*64];
__device__ __align__(16) float g_g1_whhT[128*512];
__device__ __align__(16) float g_g1_wih[512];
__device__ __align__(16) float g_g1_bih[512];
__device__ __align__(16) float g_g1_bhh[512];
__device__ __align__(16) float g_g2_wihT[128*160];
__device__ __align__(16) float g_g2_whhT[50*160];
__device__ __align__(16) float g_h1out[(size_t)T_SZ*B_SZ*256];        // [t][b][256]
__device__ __align__(16) float g_preact[2][(size_t)T_SZ*B_SZ*512];    // [dir][t*B+b][512]
__device__ __align__(16) float g_hn[4][B_SZ*128];
__device__ __align__(16) float g_hidden[B_SZ*128];

__device__ __forceinline__ float sigf(float x){ return 1.0f/(1.0f + expf(-x)); }

// ---------------- weight permutation (gate-quad layout: col = h*4+q) ----------------
__global__ void k_prep(
    const float* __restrict__ l1_wih_f, const float* __restrict__ l1_whh_f, const float* __restrict__ l1_b_f,
    const float* __restrict__ l1_wih_b, const float* __restrict__ l1_whh_b, const float* __restrict__ l1_b_b,
    const float* __restrict__ l2_wih_f, const float* __restrict__ l2_whh_f, const float* __restrict__ l2_b_f,
    const float* __restrict__ l2_wih_b, const float* __restrict__ l2_whh_b, const float* __restrict__ l2_b_b,
    const float* __restrict__ fc1_w, const float* __restrict__ fc2_w,
    const float* __restrict__ g1_wih, const float* __restrict__ g1_whh,
    const float* __restrict__ g1_bih, const float* __restrict__ g1_bhh,
    const float* __restrict__ g2_wih, const float* __restrict__ g2_whh)
{
    const int idx = blockIdx.x*blockDim.x + threadIdx.x;
    const int stride = gridDim.x*blockDim.x;

    for (int i=idx; i<2*128*512; i+=stride){
        int dir=i>>16, r=i&65535, k=r>>9, col=r&511, h=col>>2, q=col&3;
        const float* s = dir ? l1_whh_b : l1_whh_f;
        g_l1_whhT[dir][r] = s[(q*128+h)*128 + k];
    }
    for (int i=idx; i<2*128*512; i+=stride){
        int dir=i>>16, r=i&65535, k=r>>9, col=r&511, h=col>>2, q=col&3;
        const float* s = dir ? l2_whh_b : l2_whh_f;
        g_l2_whhT[dir][r] = s[(q*128+h)*128 + k];
    }
    for (int i=idx; i<2*256*512; i+=stride){
        int dir=i>>17, r=i&131071, k=r>>9, col=r&511, h=col>>2, q=col&3;
        const float* s = dir ? l2_wih_b : l2_wih_f;
        g_l2_wihT[dir][r] = s[(q*128+h)*256 + k];
    }
    for (int i=idx; i<2*512; i+=stride){
        int dir=i>>9, col=i&511, h=col>>2, q=col&3, g=q*128+h;
        g_l1_wih[dir][col] = (dir ? l1_wih_b : l1_wih_f)[g];
        g_l1_b  [dir][col] = (dir ? l1_b_b   : l1_b_f  )[g];
        g_l2_b  [dir][col] = (dir ? l2_b_b   : l2_b_f  )[g];
    }
    for (int i=idx; i<256*256; i+=stride){
        int c=i>>8, j=i&255;
        g_fc1_wT[i] = fc1_w[j*256+c];
    }
    for (int i=idx; i<256*64; i+=stride){
        int c=i>>6, j=i&63;
        g_fc2_wT[i] = fc2_w[j*256+c];
    }
    for (int i=idx; i<128*512; i+=stride){
        int k=i>>9, col=i&511, h=col>>2, q=col&3;
        g_g1_whhT[i] = (q<3) ? g1_whh[(q*128+h)*128 + k] : 0.0f;
    }
    for (int i=idx; i<512; i+=stride){
        int h=i>>2, q=i&3;
        g_g1_wih[i] = (q<3) ? g1_wih[q*128+h] : 0.0f;
        g_g1_bih[i] = (q<3) ? g1_bih[q*128+h] : 0.0f;
        g_g1_bhh[i] = (q<3) ? g1_bhh[q*128+h] : 0.0f;
    }
    for (int i=idx; i<128*160; i+=stride){
        int k=i/160, g=i%160;
        g_g2_wihT[i] = (g<150) ? g2_wih[g*128+k] : 0.0f;
    }
    for (int i=idx; i<50*160; i+=stride){
        int k=i/160, g=i%160;
        g_g2_whhT[i] = (g<150) ? g2_whh[g*50+k] : 0.0f;
    }
}

// ---------------- BiLSTM layer 1 (input dim 1), FFMA2 ----------------
__global__ void __launch_bounds__(128) k_lstm1(const float* __restrict__ edge)
{
    const int dir = blockIdx.y;
    const int b0  = blockIdx.x * NB;
    const int hh  = threadIdx.x;

    __shared__ float sh_x[NB][T_SZ];
    __shared__ u64   sh_h[NB][128];     // duplicated {h,h}

    for (int i = hh; i < NB*T_SZ; i += 128){
        int b = i / T_SZ, t = i % T_SZ;
        sh_x[b][t] = edge[(b0+b)*T_SZ + t];
    }
    #pragma unroll
    for (int b=0;b<NB;b++) sh_h[b][hh] = 0ull;
    float c[NB];
    #pragma unroll
    for (int b=0;b<NB;b++) c[b] = 0.0f;

    const ulonglong2* __restrict__ W = (const ulonglong2*)g_l1_whhT[dir];
    const u64* wib = (const u64*)g_l1_wih[dir];
    const u64* bbp = (const u64*)g_l1_b[dir];
    const u64 wi01 = wib[2*hh], wi23 = wib[2*hh+1];
    const u64 b01  = bbp[2*hh], b23  = bbp[2*hh+1];
    __syncthreads();

    for (int s=0; s<T_SZ; s++){
        const int t = dir ? (T_SZ-1-s) : s;
        u64 a01[NB], a23[NB];
        #pragma unroll
        for (int b=0;b<NB;b++){
            float xv = sh_x[b][t];
            u64 x2 = pack2(xv, xv);
            a01[b] = b01; ffma2(a01[b], wi01, x2);
            a23[b] = b23; ffma2(a23[b], wi23, x2);
        }
        #pragma unroll 4
        for (int k=0;k<128;k++){
            ulonglong2 w = W[k*128 + hh];
            #pragma unroll
            for (int b=0;b<NB;b++){
                u64 hv = sh_h[b][k];
                ffma2(a01[b], w.x, hv);
                ffma2(a23[b], w.y, hv);
            }
        }
        __syncthreads();
        float* outp = g_h1out + (size_t)t*(B_SZ*256) + (size_t)b0*256 + dir*128 + hh;
        #pragma unroll
        for (int b=0;b<NB;b++){
            float2 g01 = unpack2(a01[b]);
            float2 g23 = unpack2(a23[b]);
            float ig = sigf(g01.x);
            float fg = sigf(g01.y);
            float gg = tanhf(g23.x);
            float og = sigf(g23.y);
            c[b] = fmaf(fg, c[b], ig*gg);
            float h = og * tanhf(c[b]);
            sh_h[b][hh] = pack2(h, h);
            outp[b*256] = h;
        }
        __syncthreads();
    }
    #pragma unroll
    for (int b=0;b<NB;b++) g_hn[dir][(b0+b)*128 + hh] = unpack2(sh_h[b][hh]).x;
}

// ---------------- L2 input projection as a GEMM: preact = h1out @ wih^T + b ----------------
// Tile 128 rows x 128 cols, K=256 in slabs of 32. FFMA2 over row pairs.
__global__ void __launch_bounds__(256) k_proj()
{
    const int dir = blockIdx.z;
    const int cb  = blockIdx.y * 128;
    const size_t r0 = (size_t)blockIdx.x * 128;
    const int tid = threadIdx.x;
    const int g   = tid & 15;      // row-pair group (strided rp = g + 16*i)
    const int cg  = tid >> 4;      // col group
    const int c0  = cg * 8;

    __shared__ u64   sxp[64][33];       // [rp][k], stride 33 u64 -> conflict-free reads
    __shared__ float sw[32][132];       // [k][col]

    // accumulators: 4 row-pairs x 8 cols, init with bias duplicated over row pair
    u64 acc[4][8];
    {
        float4 bb0 = *(const float4*)&g_l2_b[dir][cb + c0];
        float4 bb1 = *(const float4*)&g_l2_b[dir][cb + c0 + 4];
        #pragma unroll
        for (int i=0;i<4;i++){
            acc[i][0]=pack2(bb0.x,bb0.x); acc[i][1]=pack2(bb0.y,bb0.y);
            acc[i][2]=pack2(bb0.z,bb0.z); acc[i][3]=pack2(bb0.w,bb0.w);
            acc[i][4]=pack2(bb1.x,bb1.x); acc[i][5]=pack2(bb1.y,bb1.y);
            acc[i][6]=pack2(bb1.z,bb1.z); acc[i][7]=pack2(bb1.w,bb1.w);
        }
    }

    const int frp = tid >> 2;            // 0..63 (x fill: row pair)
    const int fkc = (tid & 3) * 8;       // k chunk
    const int wk  = tid >> 3;            // 0..31 (w fill: k row)
    const int wc  = (tid & 7) * 16;      // col chunk

    for (int ks=0; ks<256; ks+=32){
        __syncthreads();
        // fill x slab (pack row pairs)
        {
            const float* xa = g_h1out + (r0 + 2*frp)*256 + ks + fkc;
            const float* xb = xa + 256;
            float4 a0 = *(const float4*)xa,     a1 = *(const float4*)(xa+4);
            float4 bq0 = *(const float4*)xb,    bq1 = *(const float4*)(xb+4);
            sxp[frp][fkc+0] = pack2(a0.x, bq0.x);
            sxp[frp][fkc+1] = pack2(a0.y, bq0.y);
            sxp[frp][fkc+2] = pack2(a0.z, bq0.z);
            sxp[frp][fkc+3] = pack2(a0.w, bq0.w);
            sxp[frp][fkc+4] = pack2(a1.x, bq1.x);
            sxp[frp][fkc+5] = pack2(a1.y, bq1.y);
            sxp[frp][fkc+6] = pack2(a1.z, bq1.z);
            sxp[frp][fkc+7] = pack2(a1.w, bq1.w);
        }
        // fill w slab
        {
            const float* wsrc = g_l2_wihT[dir] + (size_t)(ks+wk)*512 + cb + wc;
            float4 w0 = *(const float4*)wsrc;
            float4 w1 = *(const float4*)(wsrc+4);
            float4 w2 = *(const float4*)(wsrc+8);
            float4 w3 = *(const float4*)(wsrc+12);
            *(float4*)&sw[wk][wc+0]  = w0;
            *(float4*)&sw[wk][wc+4]  = w1;
            *(float4*)&sw[wk][wc+8]  = w2;
            *(float4*)&sw[wk][wc+12] = w3;
        }
        __syncthreads();

        #pragma unroll 4
        for (int k=0;k<32;k++){
            u64 x2[4];
            #pragma unroll
            for (int i=0;i<4;i++) x2[i] = sxp[g + 16*i][k];
            float4 w0 = *(const float4*)&sw[k][c0];
            float4 w1 = *(const float4*)&sw[k][c0+4];
            u64 wd[8];
            wd[0]=pack2(w0.x,w0.x); wd[1]=pack2(w0.y,w0.y);
            wd[2]=pack2(w0.z,w0.z); wd[3]=pack2(w0.w,w0.w);
            wd[4]=pack2(w1.x,w1.x); wd[5]=pack2(w1.y,w1.y);
            wd[6]=pack2(w1.z,w1.z); wd[7]=pack2(w1.w,w1.w);
            #pragma unroll
            for (int i=0;i<4;i++){
                #pragma unroll
                for (int j=0;j<8;j++) ffma2(acc[i][j], x2[i], wd[j]);
            }
        }
    }

    // epilogue: unpack row pairs and store
    #pragma unroll
    for (int i=0;i<4;i++){
        size_t rowA = r0 + 2*(size_t)(g + 16*i);
        float oa[8], ob[8];
        #pragma unroll
        for (int j=0;j<8;j++){
            float2 v = unpack2(acc[i][j]);
            oa[j] = v.x; ob[j] = v.y;
        }
        float* pA = g_preact[dir] + rowA*512 + cb + c0;
        float* pB = pA + 512;
        *(float4*)pA     = make_float4(oa[0],oa[1],oa[2],oa[3]);
        *(float4*)(pA+4) = make_float4(oa[4],oa[5],oa[6],oa[7]);
        *(float4*)pB     = make_float4(ob[0],ob[1],ob[2],ob[3]);
        *(float4*)(pB+4) = make_float4(ob[4],ob[5],ob[6],ob[7]);
    }
}

// ---------------- BiLSTM layer 2: recurrent part only (reads preact) ----------------
__global__ void __launch_bounds__(128) k_lstm2()
{
    const int dir = blockIdx.y;
    const int b0  = blockIdx.x * NB;
    const int hh  = threadIdx.x;

    __shared__ u64 sh_h[NB][128];       // duplicated h pairs

    #pragma unroll
    for (int b=0;b<NB;b++) sh_h[b][hh] = 0ull;
    float c[NB];
    #pragma unroll
    for (int b=0;b<NB;b++) c[b] = 0.0f;

    const ulonglong2* __restrict__ Wh = (const ulonglong2*)g_l2_whhT[dir];
    const float* __restrict__ pre = g_preact[dir];
    __syncthreads();

    for (int s=0; s<T_SZ; s++){
        const int t = dir ? (T_SZ-1-s) : s;

        // issue preact loads early (bias + Wx*x already included)
        float4 p[NB];
        #pragma unroll
        for (int b=0;b<NB;b++)
            p[b] = ((const float4*)(pre + ((size_t)t*B_SZ + b0 + b)*512))[hh];

        u64 a01[NB], a23[NB];
        #pragma unroll
        for (int b=0;b<NB;b++){ a01[b] = 0ull; a23[b] = 0ull; }

        #pragma unroll 4
        for (int k=0;k<128;k++){
            ulonglong2 w = Wh[k*128 + hh];
            #pragma unroll
            for (int b=0;b<NB;b++){
                u64 hv = sh_h[b][k];
                ffma2(a01[b], w.x, hv);
                ffma2(a23[b], w.y, hv);
            }
        }
        __syncthreads();   // all sh_h reads done
        #pragma unroll
        for (int b=0;b<NB;b++){
            float2 g01 = unpack2(a01[b]);
            float2 g23 = unpack2(a23[b]);
            float ig = sigf(g01.x + p[b].x);
            float fg = sigf(g01.y + p[b].y);
            float gg = tanhf(g23.x + p[b].z);
            float og = sigf(g23.y + p[b].w);
            c[b] = fmaf(fg, c[b], ig*gg);
            float h = og * tanhf(c[b]);
            sh_h[b][hh] = pack2(h, h);
        }
        __syncthreads();
    }
    #pragma unroll
    for (int b=0;b<NB;b++) g_hn[2+dir][(b0+b)*128 + hh] = unpack2(sh_h[b][hh]).x;
}

// ---------------- FC head ----------------
__global__ void __launch_bounds__(256) k_fc(const int* __restrict__ node_data,
                                            const float* __restrict__ emb,
                                            const float* __restrict__ fc1_b,
                                            const float* __restrict__ fc2_b)
{
    const int r = blockIdx.x;
    const int c = threadIdx.x;
    __shared__ float sh_in[256];
    __shared__ float sh_mid[256];

    int d = r >> 10;
    int b = ((r & 1023) << 1) + (c >> 7);
    int k = c & 127;
    sh_in[c] = g_hn[d][b*128 + k] + g_hn[2+d][b*128 + k];
    __syncthreads();

    float acc = fc1_b[c];
    #pragma unroll 4
    for (int i=0;i<256;i++) acc = fmaf(sh_in[i], g_fc1_wT[i*256 + c], acc);
    sh_mid[c] = sigf(acc);
    __syncthreads();

    if (c < 64){
        float a2 = fc2_b[c];
        #pragma unroll 4
        for (int i=0;i<256;i++) a2 = fmaf(sh_mid[i], g_fc2_wT[i*64 + c], a2);
        g_hidden[r*128 + c] = sigf(a2);
    } else if (c < 128){
        int e = c - 64;
        int n0 = node_data[r*2], n1 = node_data[r*2+1];
        g_hidden[r*128 + 64 + e] = 0.5f*(emb[n0*64 + e] + emb[n1*64 + e]);
    }
}

// ---------------- decoder: GRU(128) -> GRU(50) -> sigmoid, 200 steps ----------------
__global__ void __launch_bounds__(160) k_dec(const float* __restrict__ edge,
                                             const float* __restrict__ g2_bih,
                                             const float* __restrict__ g2_bhh,
                                             const float* __restrict__ dec_w,
                                             const float* __restrict__ dec_b,
                                             float* __restrict__ out)
{
    const int b0  = blockIdx.x * NB;
    const int tid = threadIdx.x;     // 0..159

    __shared__ u64   h1d[NB][128];   // h1 duplicated {h,h}
    __shared__ u64   h1p[128][8];    // h1 batch pairs {h_b0,h_b1}
    __shared__ u64   h2p[52][8];     // h2 batch pairs
    __shared__ float h2s[NB][52];
    __shared__ float s_rz[NB][100];
    __shared__ float s_in[NB][52];
    __shared__ float s_hn[NB][52];
    __shared__ float res[NB];
    __shared__ float dw[52];

    if (tid < 128){
        float v[NB];
        #pragma unroll
        for (int b=0;b<NB;b++){
            v[b] = g_hidden[(b0+b)*128 + tid];
            h1d[b][tid] = pack2(v[b], v[b]);
        }
        #pragma unroll
        for (int bp=0;bp<8;bp++) h1p[tid][bp] = pack2(v[2*bp], v[2*bp+1]);
    }
    if (tid < 52){
        #pragma unroll
        for (int b=0;b<NB;b++) h2s[b][tid] = 0.0f;
        #pragma unroll
        for (int bp=0;bp<8;bp++) h2p[tid][bp] = 0ull;
        dw[tid] = (tid < 50) ? dec_w[tid] : 0.0f;
    }
    if (tid < NB) res[tid] = edge[(b0+tid)*T_SZ + (T_SZ-1)];

    float4 wi = {0,0,0,0}, bi = {0,0,0,0}, bh = {0,0,0,0};
    if (tid < 128){
        wi = ((const float4*)g_g1_wih)[tid];
        bi = ((const float4*)g_g1_bih)[tid];
        bh = ((const float4*)g_g1_bhh)[tid];
    }
    float g2bi = 0.0f, g2bh = 0.0f;
    if (tid < 150){ g2bi = g2_bih[tid]; g2bh = g2_bhh[tid]; }
    const float decb = dec_b[0];
    __syncthreads();

    for (int t=0; t<T_SZ; t++){
        // Phase A: GRU1 matvec (reads h1d), FFMA2 over gate pairs
        u64 a01[NB], a23[NB];
        if (tid < 128){
            const u64 bh01 = pack2(bh.x, bh.y);
            const u64 bh23 = pack2(bh.z, bh.w);
            #pragma unroll
            for (int b=0;b<NB;b++){ a01[b] = bh01; a23[b] = bh23; }
            const ulonglong2* __restrict__ W = (const ulonglong2*)g_g1_whhT;
            #pragma unroll 4
            for (int k=0;k<128;k++){
                ulonglong2 w = W[k*128 + tid];
                #pragma unroll
                for (int b=0;b<NB;b++){
                    u64 hv = h1d[b][k];
                    ffma2(a01[b], w.x, hv);
                    ffma2(a23[b], w.y, hv);
                }
            }
        }
        __syncthreads();   // all h1d reads complete before in-place update

        if (tid < 128){
            float hn_[NB];
            #pragma unroll
            for (int b=0;b<NB;b++){
                float2 g01 = unpack2(a01[b]);
                float2 g23 = unpack2(a23[b]);
                float rv  = res[b];
                float ir  = fmaf(rv, wi.x, bi.x);
                float iz  = fmaf(rv, wi.y, bi.y);
                float inn = fmaf(rv, wi.z, bi.z);
                float rg = sigf(ir + g01.x);
                float zg = sigf(iz + g01.y);
                float ng = tanhf(fmaf(rg, g23.x, inn));
                float h1 = unpack2(h1d[b][tid]).x;
                hn_[b] = fmaf(zg, h1 - ng, ng);
            }
            #pragma unroll
            for (int b=0;b<NB;b++) h1d[b][tid] = pack2(hn_[b], hn_[b]);
            #pragma unroll
            for (int bp=0;bp<8;bp++) h1p[tid][bp] = pack2(hn_[2*bp], hn_[2*bp+1]);
        }
        __syncthreads();

        // Phase B: GRU2 pre-activations, FFMA2 over batch pairs (150 gate threads)
        if (tid < 150){
            u64 gi2[8], gh2[8];
            const u64 bi2 = pack2(g2bi, g2bi);
            const u64 bh2 = pack2(g2bh, g2bh);
            #pragma unroll
            for (int bp=0;bp<8;bp++){ gi2[bp] = bi2; gh2[bp] = bh2; }
            #pragma unroll 4
            for (int k=0;k<128;k++){
                float w = g_g2_wihT[k*160 + tid];
                u64 w2 = pack2(w, w);
                #pragma unroll
                for (int bp=0;bp<8;bp++) ffma2(gi2[bp], h1p[k][bp], w2);
            }
            #pragma unroll 2
            for (int k=0;k<50;k++){
                float w = g_g2_whhT[k*160 + tid];
                u64 w2 = pack2(w, w);
                #pragma unroll
                for (int bp=0;bp<8;bp++) ffma2(gh2[bp], h2p[k][bp], w2);
            }
            if (tid < 100){
                #pragma unroll
                for (int bp=0;bp<8;bp++){
                    float2 a = unpack2(gi2[bp]);
                    float2 b = unpack2(gh2[bp]);
                    s_rz[2*bp][tid]   = a.x + b.x;
                    s_rz[2*bp+1][tid] = a.y + b.y;
                }
            } else {
                int n = tid - 100;
                #pragma unroll
                for (int bp=0;bp<8;bp++){
                    float2 a = unpack2(gi2[bp]);
                    float2 b = unpack2(gh2[bp]);
                    s_in[2*bp][n]   = a.x;  s_hn[2*bp][n]   = b.x;
                    s_in[2*bp+1][n] = a.y;  s_hn[2*bp+1][n] = b.y;
                }
            }
        }
        __syncthreads();

        // Phase C: GRU2 combine (50 threads)
        if (tid < 50){
            float h2n[NB];
            #pragma unroll
            for (int b=0;b<NB;b++){
                float rg = sigf(s_rz[b][tid]);
                float zg = sigf(s_rz[b][50+tid]);
                float ng = tanhf(fmaf(rg, s_hn[b][tid], s_in[b][tid]));
                float h2 = h2s[b][tid];
                h2n[b] = fmaf(zg, h2 - ng, ng);
                h2s[b][tid] = h2n[b];
            }
            #pragma unroll
            for (int bp=0;bp<8;bp++) h2p[tid][bp] = pack2(h2n[2*bp], h2n[2*bp+1]);
        }
        __syncthreads();

        // Phase D: decoder dot + sigmoid (16 threads)
        if (tid < NB){
            float s = decb;
            #pragma unroll 2
            for (int k=0;k<50;k++) s = fmaf(h2s[tid][k], dw[k], s);
            float r = sigf(s);
            res[tid] = r;
            out[(b0+tid)*T_SZ + t] = r;
        }
        __syncthreads();
    }
}

extern "C" void kernel_launch(void* const* d_in, const int* in_sizes, int n_in,
                              void* d_out, int out_size)
{
    const int*   node_data = (const int*)  d_in[0];
    const float* edge_data = (const float*)d_in[1];
    const float* emb       = (const float*)d_in[2];
    const float* l1_wih_f  = (const float*)d_in[3];
    const float* l1_whh_f  = (const float*)d_in[4];
    const float* l1_b_f    = (const float*)d_in[5];
    const float* l1_wih_b  = (const float*)d_in[6];
    const float* l1_whh_b  = (const float*)d_in[7];
    const float* l1_b_b    = (const float*)d_in[8];
    const float* l2_wih_f  = (const float*)d_in[9];
    const float* l2_whh_f  = (const float*)d_in[10];
    const float* l2_b_f    = (const float*)d_in[11];
    const float* l2_wih_b  = (const float*)d_in[12];
    const float* l2_whh_b  = (const float*)d_in[13];
    const float* l2_b_b    = (const float*)d_in[14];
    const float* fc1_w     = (const float*)d_in[15];
    const float* fc1_b     = (const float*)d_in[16];
    const float* fc2_w     = (const float*)d_in[17];
    const float* fc2_b     = (const float*)d_in[18];
    const float* g1_wih    = (const float*)d_in[19];
    const float* g1_whh    = (const float*)d_in[20];
    const float* g1_bih    = (const float*)d_in[21];
    const float* g1_bhh    = (const float*)d_in[22];
    const float* g2_wih    = (const float*)d_in[23];
    const float* g2_whh    = (const float*)d_in[24];
    const float* g2_bih    = (const float*)d_in[25];
    const float* g2_bhh    = (const float*)d_in[26];
    const float* dec_w     = (const float*)d_in[27];
    const float* dec_b     = (const float*)d_in[28];
    float* out = (float*)d_out;

    k_prep<<<256, 256>>>(l1_wih_f, l1_whh_f, l1_b_f, l1_wih_b, l1_whh_b, l1_b_b,
                         l2_wih_f, l2_whh_f, l2_b_f, l2_wih_b, l2_whh_b, l2_b_b,
                         fc1_w, fc2_w, g1_wih, g1_whh, g1_bih, g1_bhh,
                         g2_wih, g2_whh);
    k_lstm1<<<dim3(B_SZ/NB, 2), 128>>>(edge_data);
    k_proj<<<dim3((T_SZ*B_SZ)/128, 4, 2), 256>>>();
    k_lstm2<<<dim3(B_SZ/NB, 2), 128>>>();
    k_fc<<<B_SZ, 256>>>(node_data, emb, fc1_b, fc2_b);
    k_dec<<<B_SZ/NB, 160>>>(edge_data, g2_bih, g2_bhh, dec_w, dec_b, out);
}

// round 11
// speedup vs baseline: 1.0642x; 1.0642x over previous
#include <cuda_runtime.h>
#include <math.h>

#define B_SZ 2048
#define T_SZ 200
#define NB   16

typedef unsigned long long u64;

// ---- packed fp32x2 helpers (SASS FFMA2: only reachable via PTX) ----
__device__ __forceinline__ void ffma2(u64 &d, u64 a, u64 b){
    asm("fma.rn.f32x2 %0, %1, %2, %0;" : "+l"(d) : "l"(a), "l"(b));
}
__device__ __forceinline__ u64 pack2(float lo, float hi){
    u64 r; asm("mov.b64 %0, {%1, %2};" : "=l"(r) : "f"(lo), "f"(hi)); return r;
}
__device__ __forceinline__ float2 unpack2(u64 v){
    float2 r; asm("mov.b64 {%0, %1}, %2;" : "=f"(r.x), "=f"(r.y) : "l"(v)); return r;
}

// ---- fast activations: MUFU-based, rel err ~1e-6 ----
__device__ __forceinline__ float fex2(float x){ float r; asm("ex2.approx.f32 %0, %1;" : "=f"(r) : "f"(x)); return r; }
__device__ __forceinline__ float frcp(float x){ float r; asm("rcp.approx.f32 %0, %1;" : "=f"(r) : "f"(x)); return r; }
#define LOG2E 1.4426950408889634f
__device__ __forceinline__ float sigf(float x){
    return frcp(1.0f + fex2(-LOG2E*x));
}
__device__ __forceinline__ float tanhfast(float x){
    float t = fminf(2.0f*LOG2E*x, 126.0f);   // avoid inf*0 NaN for huge x
    float e = fex2(t);
    return (e - 1.0f) * frcp(e + 1.0f);
}

// ---------------- device scratch ----------------
__device__ __align__(16) float g_l1_whhT[2][128*512];
__device__ __align__(16) float g_l1_wih [2][512];
__device__ __align__(16) float g_l1_b   [2][512];
__device__ __align__(16) float g_l2_wihT[2][256*512];
__device__ __align__(16) float g_l2_whhT[2][128*512];
__device__ __align__(16) float g_l2_b   [2][512];
__device__ __align__(16) float g_fc1_wT[256*256];
__device__ __align__(16) float g_fc2_wT[256*64];
__device__ __align__(16) float g_g1_whhT[128*512];
__device__ __align__(16) float g_g1_wih[512];
__device__ __align__(16) float g_g1_bih[512];
__device__ __align__(16) float g_g1_bhh[512];
__device__ __align__(16) float g_g2_wihT[128*160];
__device__ __align__(16) float g_g2_whhT[50*160];
__device__ __align__(16) float g_h1out[(size_t)T_SZ*B_SZ*256];  // [t][b][256] plain
__device__ __align__(16) float g_hn[4][B_SZ*128];
__device__ __align__(16) float g_hidden[B_SZ*128];

// ---------------- weight permutation (gate-quad layout: col = h*4+q) ----------------
__global__ void k_prep(
    const float* __restrict__ l1_wih_f, const float* __restrict__ l1_whh_f, const float* __restrict__ l1_b_f,
    const float* __restrict__ l1_wih_b, const float* __restrict__ l1_whh_b, const float* __restrict__ l1_b_b,
    const float* __restrict__ l2_wih_f, const float* __restrict__ l2_whh_f, const float* __restrict__ l2_b_f,
    const float* __restrict__ l2_wih_b, const float* __restrict__ l2_whh_b, const float* __restrict__ l2_b_b,
    const float* __restrict__ fc1_w, const float* __restrict__ fc2_w,
    const float* __restrict__ g1_wih, const float* __restrict__ g1_whh,
    const float* __restrict__ g1_bih, const float* __restrict__ g1_bhh,
    const float* __restrict__ g2_wih, const float* __restrict__ g2_whh)
{
    const int idx = blockIdx.x*blockDim.x + threadIdx.x;
    const int stride = gridDim.x*blockDim.x;

    for (int i=idx; i<2*128*512; i+=stride){
        int dir=i>>16, r=i&65535, k=r>>9, col=r&511, h=col>>2, q=col&3;
        const float* s = dir ? l1_whh_b : l1_whh_f;
        g_l1_whhT[dir][r] = s[(q*128+h)*128 + k];
    }
    for (int i=idx; i<2*128*512; i+=stride){
        int dir=i>>16, r=i&65535, k=r>>9, col=r&511, h=col>>2, q=col&3;
        const float* s = dir ? l2_whh_b : l2_whh_f;
        g_l2_whhT[dir][r] = s[(q*128+h)*128 + k];
    }
    for (int i=idx; i<2*256*512; i+=stride){
        int dir=i>>17, r=i&131071, k=r>>9, col=r&511, h=col>>2, q=col&3;
        const float* s = dir ? l2_wih_b : l2_wih_f;
        g_l2_wihT[dir][r] = s[(q*128+h)*256 + k];
    }
    for (int i=idx; i<2*512; i+=stride){
        int dir=i>>9, col=i&511, h=col>>2, q=col&3, g=q*128+h;
        g_l1_wih[dir][col] = (dir ? l1_wih_b : l1_wih_f)[g];
        g_l1_b  [dir][col] = (dir ? l1_b_b   : l1_b_f  )[g];
        g_l2_b  [dir][col] = (dir ? l2_b_b   : l2_b_f  )[g];
    }
    for (int i=idx; i<256*256; i+=stride){
        int c=i>>8, j=i&255;
        g_fc1_wT[i] = fc1_w[j*256+c];
    }
    for (int i=idx; i<256*64; i+=stride){
        int c=i>>6, j=i&63;
        g_fc2_wT[i] = fc2_w[j*256+c];
    }
    for (int i=idx; i<128*512; i+=stride){
        int k=i>>9, col=i&511, h=col>>2, q=col&3;
        g_g1_whhT[i] = (q<3) ? g1_whh[(q*128+h)*128 + k] : 0.0f;
    }
    for (int i=idx; i<512; i+=stride){
        int h=i>>2, q=i&3;
        g_g1_wih[i] = (q<3) ? g1_wih[q*128+h] : 0.0f;
        g_g1_bih[i] = (q<3) ? g1_bih[q*128+h] : 0.0f;
        g_g1_bhh[i] = (q<3) ? g1_bhh[q*128+h] : 0.0f;
    }
    for (int i=idx; i<128*160; i+=stride){
        int k=i/160, g=i%160;
        g_g2_wihT[i] = (g<150) ? g2_wih[g*128+k] : 0.0f;
    }
    for (int i=idx; i<50*160; i+=stride){
        int k=i/160, g=i%160;
        g_g2_whhT[i] = (g<150) ? g2_whh[g*50+k] : 0.0f;
    }
}

// ---------------- BiLSTM layer 1 (input dim 1): transposed h state ----------------
// sh_hT[k][b]: rows of 18 u64 (144B, 16B-aligned). Reads are warp-broadcast LDS.128.
__global__ void __launch_bounds__(128) k_lstm1(const float* __restrict__ edge)
{
    const int dir = blockIdx.y;
    const int b0  = blockIdx.x * NB;
    const int hh  = threadIdx.x;

    __shared__ float sh_x[NB][T_SZ];
    __shared__ u64   sh_hT[128][18];

    for (int i = hh; i < NB*T_SZ; i += 128){
        int b = i / T_SZ, t = i % T_SZ;
        sh_x[b][t] = edge[(b0+b)*T_SZ + t];
    }
    #pragma unroll
    for (int j=0;j<NB;j++) sh_hT[hh][j] = 0ull;
    float c[NB];
    #pragma unroll
    for (int b=0;b<NB;b++) c[b] = 0.0f;
    float hb[NB];

    const ulonglong2* __restrict__ W = (const ulonglong2*)g_l1_whhT[dir];
    const u64* wib = (const u64*)g_l1_wih[dir];
    const u64* bbp = (const u64*)g_l1_b[dir];
    const u64 wi01 = wib[2*hh], wi23 = wib[2*hh+1];
    const u64 b01  = bbp[2*hh], b23  = bbp[2*hh+1];
    __syncthreads();

    for (int s=0; s<T_SZ; s++){
        const int t = dir ? (T_SZ-1-s) : s;
        u64 a01[NB], a23[NB];
        #pragma unroll
        for (int b=0;b<NB;b++){
            float xv = sh_x[b][t];
            u64 x2 = pack2(xv, xv);
            a01[b] = b01; ffma2(a01[b], wi01, x2);
            a23[b] = b23; ffma2(a23[b], wi23, x2);
        }
        #pragma unroll 4
        for (int k=0;k<128;k++){
            ulonglong2 w = W[k*128 + hh];
            const ulonglong2* hrow = (const ulonglong2*)sh_hT[k];
            #pragma unroll
            for (int j=0;j<8;j++){
                ulonglong2 hp = hrow[j];
                ffma2(a01[2*j],   w.x, hp.x);
                ffma2(a23[2*j],   w.y, hp.x);
                ffma2(a01[2*j+1], w.x, hp.y);
                ffma2(a23[2*j+1], w.y, hp.y);
            }
        }
        __syncthreads();
        float* outp = g_h1out + (size_t)t*(B_SZ*256) + (size_t)b0*256 + dir*128 + hh;
        #pragma unroll
        for (int b=0;b<NB;b++){
            float2 g01 = unpack2(a01[b]);
            float2 g23 = unpack2(a23[b]);
            float ig = sigf(g01.x);
            float fg = sigf(g01.y);
            float gg = tanhfast(g23.x);
            float og = sigf(g23.y);
            c[b] = fmaf(fg, c[b], ig*gg);
            hb[b] = og * tanhfast(c[b]);
            outp[b*256] = hb[b];
        }
        ulonglong2* myrow = (ulonglong2*)sh_hT[hh];
        #pragma unroll
        for (int j=0;j<8;j++)
            myrow[j] = make_ulonglong2(pack2(hb[2*j],hb[2*j]), pack2(hb[2*j+1],hb[2*j+1]));
        __syncthreads();
    }
    #pragma unroll
    for (int b=0;b<NB;b++) g_hn[dir][(b0+b)*128 + hh] = hb[b];
}

// ---------------- BiLSTM layer 2 (input 256 fused), R8 layout (48KB smem cap) ----------------
__global__ void __launch_bounds__(128) k_lstm2()
{
    const int dir = blockIdx.y;
    const int b0  = blockIdx.x * NB;
    const int hh  = threadIdx.x;

    __shared__ u64 sh_x[NB*256];        // duplicated input pairs (32KB)
    __shared__ u64 sh_h[NB][128];       // duplicated h pairs (16KB)

    #pragma unroll
    for (int b=0;b<NB;b++) sh_h[b][hh] = 0ull;
    float c[NB];
    #pragma unroll
    for (int b=0;b<NB;b++) c[b] = 0.0f;

    const ulonglong2* __restrict__ Wx = (const ulonglong2*)g_l2_wihT[dir];
    const ulonglong2* __restrict__ Wh = (const ulonglong2*)g_l2_whhT[dir];
    const u64* bbp = (const u64*)g_l2_b[dir];
    const u64 b01 = bbp[2*hh], b23 = bbp[2*hh+1];

    for (int s=0; s<T_SZ; s++){
        const int t = dir ? (T_SZ-1-s) : s;
        __syncthreads();
        // fill sh_x with duplicated pairs from plain h1out
        const float4* __restrict__ src =
            (const float4*)(g_h1out + (size_t)t*(B_SZ*256) + (size_t)b0*256);
        #pragma unroll
        for (int i=0;i<8;i++){
            int f = hh + i*128;            // float4 index: b = f>>6, k0 = (f&63)*4
            float4 v = src[f];
            ulonglong2* dst = (ulonglong2*)&sh_x[(f>>6)*256 + ((f&63)<<2)];
            dst[0] = make_ulonglong2(pack2(v.x,v.x), pack2(v.y,v.y));
            dst[1] = make_ulonglong2(pack2(v.z,v.z), pack2(v.w,v.w));
        }
        __syncthreads();

        u64 a01[NB], a23[NB];
        #pragma unroll
        for (int b=0;b<NB;b++){ a01[b] = b01; a23[b] = b23; }

        #pragma unroll 4
        for (int k=0;k<256;k++){
            ulonglong2 w = Wx[k*128 + hh];
            #pragma unroll
            for (int b=0;b<NB;b++){
                u64 xv = sh_x[b*256 + k];
                ffma2(a01[b], w.x, xv);
                ffma2(a23[b], w.y, xv);
            }
        }
        #pragma unroll 4
        for (int k=0;k<128;k++){
            ulonglong2 w = Wh[k*128 + hh];
            #pragma unroll
            for (int b=0;b<NB;b++){
                u64 hv = sh_h[b][k];
                ffma2(a01[b], w.x, hv);
                ffma2(a23[b], w.y, hv);
            }
        }
        __syncthreads();
        #pragma unroll
        for (int b=0;b<NB;b++){
            float2 g01 = unpack2(a01[b]);
            float2 g23 = unpack2(a23[b]);
            float ig = sigf(g01.x);
            float fg = sigf(g01.y);
            float gg = tanhfast(g23.x);
            float og = sigf(g23.y);
            c[b] = fmaf(fg, c[b], ig*gg);
            float h = og * tanhfast(c[b]);
            sh_h[b][hh] = pack2(h, h);
        }
    }
    __syncthreads();
    #pragma unroll
    for (int b=0;b<NB;b++) g_hn[2+dir][(b0+b)*128 + hh] = unpack2(sh_h[b][hh]).x;
}

// ---------------- FC head ----------------
__global__ void __launch_bounds__(256) k_fc(const int* __restrict__ node_data,
                                            const float* __restrict__ emb,
                                            const float* __restrict__ fc1_b,
                                            const float* __restrict__ fc2_b)
{
    const int r = blockIdx.x;
    const int c = threadIdx.x;
    __shared__ float sh_in[256];
    __shared__ float sh_mid[256];

    int d = r >> 10;
    int b = ((r & 1023) << 1) + (c >> 7);
    int k = c & 127;
    sh_in[c] = g_hn[d][b*128 + k] + g_hn[2+d][b*128 + k];
    __syncthreads();

    float acc = fc1_b[c];
    #pragma unroll 4
    for (int i=0;i<256;i++) acc = fmaf(sh_in[i], g_fc1_wT[i*256 + c], acc);
    sh_mid[c] = sigf(acc);
    __syncthreads();

    if (c < 64){
        float a2 = fc2_b[c];
        #pragma unroll 4
        for (int i=0;i<256;i++) a2 = fmaf(sh_mid[i], g_fc2_wT[i*64 + c], a2);
        g_hidden[r*128 + c] = sigf(a2);
    } else if (c < 128){
        int e = c - 64;
        int n0 = node_data[r*2], n1 = node_data[r*2+1];
        g_hidden[r*128 + 64 + e] = 0.5f*(emb[n0*64 + e] + emb[n1*64 + e]);
    }
}

// ---------------- decoder: GRU(128) -> GRU(50) -> sigmoid, 200 steps ----------------
__global__ void __launch_bounds__(160) k_dec(const float* __restrict__ edge,
                                             const float* __restrict__ g2_bih,
                                             const float* __restrict__ g2_bhh,
                                             const float* __restrict__ dec_w,
                                             const float* __restrict__ dec_b,
                                             float* __restrict__ out)
{
    const int b0  = blockIdx.x * NB;
    const int tid = threadIdx.x;     // 0..159

    __shared__ u64   h1dT[128][18];  // transposed duplicated {h,h}, broadcast reads
    __shared__ u64   h1p[128][9];    // h1 batch pairs {h_b0,h_b1} (padded: 2-way max)
    __shared__ u64   h2p[52][9];     // h2 batch pairs
    __shared__ float h2s[NB][52];
    __shared__ float s_rz[NB][100];
    __shared__ float s_in[NB][52];
    __shared__ float s_hn[NB][52];
    __shared__ float res[NB];
    __shared__ float dw[52];

    if (tid < 128){
        float v[NB];
        #pragma unroll
        for (int b=0;b<NB;b++) v[b] = g_hidden[(b0+b)*128 + tid];
        ulonglong2* myrow = (ulonglong2*)h1dT[tid];
        #pragma unroll
        for (int j=0;j<8;j++)
            myrow[j] = make_ulonglong2(pack2(v[2*j],v[2*j]), pack2(v[2*j+1],v[2*j+1]));
        #pragma unroll
        for (int bp=0;bp<8;bp++) h1p[tid][bp] = pack2(v[2*bp], v[2*bp+1]);
    }
    if (tid < 52){
        #pragma unroll
        for (int b=0;b<NB;b++) h2s[b][tid] = 0.0f;
        #pragma unroll
        for (int bp=0;bp<8;bp++) h2p[tid][bp] = 0ull;
        dw[tid] = (tid < 50) ? dec_w[tid] : 0.0f;
    }
    if (tid < NB) res[tid] = edge[(b0+tid)*T_SZ + (T_SZ-1)];

    float4 wi = {0,0,0,0}, bi = {0,0,0,0}, bh = {0,0,0,0};
    if (tid < 128){
        wi = ((const float4*)g_g1_wih)[tid];
        bi = ((const float4*)g_g1_bih)[tid];
        bh = ((const float4*)g_g1_bhh)[tid];
    }
    float g2bi = 0.0f, g2bh = 0.0f;
    if (tid < 150){ g2bi = g2_bih[tid]; g2bh = g2_bhh[tid]; }
    const float decb = dec_b[0];
    __syncthreads();

    for (int t=0; t<T_SZ; t++){
        // Phase A: GRU1 matvec over transposed h1, broadcast LDS.128
        u64 a01[NB], a23[NB];
        if (tid < 128){
            const u64 bh01 = pack2(bh.x, bh.y);
            const u64 bh23 = pack2(bh.z, bh.w);
            #pragma unroll
            for (int b=0;b<NB;b++){ a01[b] = bh01; a23[b] = bh23; }
            const ulonglong2* __restrict__ W = (const ulonglong2*)g_g1_whhT;
            #pragma unroll 4
            for (int k=0;k<128;k++){
                ulonglong2 w = W[k*128 + tid];
                const ulonglong2* hrow = (const ulonglong2*)h1dT[k];
                #pragma unroll
                for (int j=0;j<8;j++){
                    ulonglong2 hp = hrow[j];
                    ffma2(a01[2*j],   w.x, hp.x);
                    ffma2(a23[2*j],   w.y, hp.x);
                    ffma2(a01[2*j+1], w.x, hp.y);
                    ffma2(a23[2*j+1], w.y, hp.y);
                }
            }
        }
        __syncthreads();   // all h1dT reads complete before overwrite

        if (tid < 128){
            float hn_[NB];
            #pragma unroll
            for (int b=0;b<NB;b++){
                float2 g01 = unpack2(a01[b]);
                float2 g23 = unpack2(a23[b]);
                float rv  = res[b];
                float ir  = fmaf(rv, wi.x, bi.x);
                float iz  = fmaf(rv, wi.y, bi.y);
                float inn = fmaf(rv, wi.z, bi.z);
                float rg = sigf(ir + g01.x);
                float zg = sigf(iz + g01.y);
                float ng = tanhfast(fmaf(rg, g23.x, inn));
                float h1 = unpack2(h1dT[tid][b]).x;
                hn_[b] = fmaf(zg, h1 - ng, ng);
            }
            ulonglong2* myrow = (ulonglong2*)h1dT[tid];
            #pragma unroll
            for (int j=0;j<8;j++)
                myrow[j] = make_ulonglong2(pack2(hn_[2*j],hn_[2*j]), pack2(hn_[2*j+1],hn_[2*j+1]));
            #pragma unroll
            for (int bp=0;bp<8;bp++) h1p[tid][bp] = pack2(hn_[2*bp], hn_[2*bp+1]);
        }
        __syncthreads();

        // Phase B: GRU2 pre-activations, FFMA2 over batch pairs (150 gate threads)
        if (tid < 150){
            u64 gi2[8], gh2[8];
            const u64 bi2 = pack2(g2bi, g2bi);
            const u64 bh2 = pack2(g2bh, g2bh);
            #pragma unroll
            for (int bp=0;bp<8;bp++){ gi2[bp] = bi2; gh2[bp] = bh2; }
            #pragma unroll 4
            for (int k=0;k<128;k++){
                float w = g_g2_wihT[k*160 + tid];
                u64 w2 = pack2(w, w);
                #pragma unroll
                for (int bp=0;bp<8;bp++) ffma2(gi2[bp], h1p[k][bp], w2);
            }
            #pragma unroll 2
            for (int k=0;k<50;k++){
                float w = g_g2_whhT[k*160 + tid];
                u64 w2 = pack2(w, w);
                #pragma unroll
                for (int bp=0;bp<8;bp++) ffma2(gh2[bp], h2p[k][bp], w2);
            }
            if (tid < 100){
                #pragma unroll
                for (int bp=0;bp<8;bp++){
                    float2 a = unpack2(gi2[bp]);
                    float2 b = unpack2(gh2[bp]);
                    s_rz[2*bp][tid]   = a.x + b.x;
                    s_rz[2*bp+1][tid] = a.y + b.y;
                }
            } else {
                int n = tid - 100;
                #pragma unroll
                for (int bp=0;bp<8;bp++){
                    float2 a = unpack2(gi2[bp]);
                    float2 b = unpack2(gh2[bp]);
                    s_in[2*bp][n]   = a.x;  s_hn[2*bp][n]   = b.x;
                    s_in[2*bp+1][n] = a.y;  s_hn[2*bp+1][n] = b.y;
                }
            }
        }
        __syncthreads();

        // Phase C: GRU2 combine (50 threads)
        if (tid < 50){
            float h2n[NB];
            #pragma unroll
            for (int b=0;b<NB;b++){
                float rg = sigf(s_rz[b][tid]);
                float zg = sigf(s_rz[b][50+tid]);
                float ng = tanhfast(fmaf(rg, s_hn[b][tid], s_in[b][tid]));
                float h2 = h2s[b][tid];
                h2n[b] = fmaf(zg, h2 - ng, ng);
                h2s[b][tid] = h2n[b];
            }
            #pragma unroll
            for (int bp=0;bp<8;bp++) h2p[tid][bp] = pack2(h2n[2*bp], h2n[2*bp+1]);
        }
        __syncthreads();

        // Phase D: decoder dot + sigmoid (16 threads)
        if (tid < NB){
            float s = decb;
            #pragma unroll 2
            for (int k=0;k<50;k++) s = fmaf(h2s[tid][k], dw[k], s);
            float r = sigf(s);
            res[tid] = r;
            out[(b0+tid)*T_SZ + t] = r;
        }
        __syncthreads();
    }
}

extern "C" void kernel_launch(void* const* d_in, const int* in_sizes, int n_in,
                              void* d_out, int out_size)
{
    const int*   node_data = (const int*)  d_in[0];
    const float* edge_data = (const float*)d_in[1];
    const float* emb       = (const float*)d_in[2];
    const float* l1_wih_f  = (const float*)d_in[3];
    const float* l1_whh_f  = (const float*)d_in[4];
    const float* l1_b_f    = (const float*)d_in[5];
    const float* l1_wih_b  = (const float*)d_in[6];
    const float* l1_whh_b  = (const float*)d_in[7];
    const float* l1_b_b    = (const float*)d_in[8];
    const float* l2_wih_f  = (const float*)d_in[9];
    const float* l2_whh_f  = (const float*)d_in[10];
    const float* l2_b_f    = (const float*)d_in[11];
    const float* l2_wih_b  = (const float*)d_in[12];
    const float* l2_whh_b  = (const float*)d_in[13];
    const float* l2_b_b    = (const float*)d_in[14];
    const float* fc1_w     = (const float*)d_in[15];
    const float* fc1_b     = (const float*)d_in[16];
    const float* fc2_w     = (const float*)d_in[17];
    const float* fc2_b     = (const float*)d_in[18];
    const float* g1_wih    = (const float*)d_in[19];
    const float* g1_whh    = (const float*)d_in[20];
    const float* g1_bih    = (const float*)d_in[21];
    const float* g1_bhh    = (const float*)d_in[22];
    const float* g2_wih    = (const float*)d_in[23];
    const float* g2_whh    = (const float*)d_in[24];
    const float* g2_bih    = (const float*)d_in[25];
    const float* g2_bhh    = (const float*)d_in[26];
    const float* dec_w     = (const float*)d_in[27];
    const float* dec_b     = (const float*)d_in[28];
    float* out = (float*)d_out;

    k_prep<<<256, 256>>>(l1_wih_f, l1_whh_f, l1_b_f, l1_wih_b, l1_whh_b, l1_b_b,
                         l2_wih_f, l2_whh_f, l2_b_f, l2_wih_b, l2_whh_b, l2_b_b,
                         fc1_w, fc2_w, g1_wih, g1_whh, g1_bih, g1_bhh,
                         g2_wih, g2_whh);
    k_lstm1<<<dim3(B_SZ/NB, 2), 128>>>(edge_data);
    k_lstm2<<<dim3(B_SZ/NB, 2), 128>>>();
    k_fc<<<B_SZ, 256>>>(node_data, emb, fc1_b, fc2_b);
    k_dec<<<B_SZ/NB, 160>>>(edge_data, g2_bih, g2_bhh, dec_w, dec_b, out);
}